// round 2
// baseline (speedup 1.0000x reference)
#include <cuda_runtime.h>

#define NN 100000
#define NE 800000
#define C 64
#define H 4

// ---- scratch (allocation-free: __device__ globals) ----
__device__ float    g_a[NN * 8];        // a_src[0..3], a_dst[0..3] per node
__device__ float    g_p[NN * 256];      // p[n, h*64+j] = h[n,:] @ proj_w[(c*4+h), j]
__device__ unsigned g_smax[NN * H];     // order-preserving-mapped float max
__device__ float    g_ssum[NN * H];
__device__ float    g_scores[NE * H];   // scores, then overwritten with exp()
__device__ float    g_agg[NN * C];      // scattered output (pre-bias)
__device__ int      g_idx64;            // edge_index dtype flag

// order-preserving float<->uint map for atomicMax
__device__ __forceinline__ unsigned fmap(float f) {
    unsigned u = __float_as_uint(f);
    return (u & 0x80000000u) ? ~u : (u | 0x80000000u);
}
__device__ __forceinline__ float funmap(unsigned u) {
    return (u & 0x80000000u) ? __uint_as_float(u & 0x7fffffffu)
                             : __uint_as_float(~u);
}

__device__ __forceinline__ int edge_idx(const void* ei, long long pos) {
    if (g_idx64) return (int)((const long long*)ei)[pos];
    return ((const int*)ei)[pos];
}

// ---- dtype probe: int64 edge_index iff first 4 int64 reads are in [0, NN) ----
__global__ void k_detect(const void* ei) {
    const long long* p = (const long long*)ei;
    bool ok = true;
    for (int i = 0; i < 4; i++) {
        long long v = p[i];
        if (v < 0 || v >= NN) ok = false;
    }
    g_idx64 = ok ? 1 : 0;
}

// ---- zero/init scratch ----
__global__ void k_init() {
    int stride = gridDim.x * blockDim.x;
    for (int i = blockIdx.x * blockDim.x + threadIdx.x; i < NN * C; i += stride) {
        g_agg[i] = 0.f;
        if (i < NN * H) { g_smax[i] = 0u; g_ssum[i] = 0.f; }
    }
}

// ---- fused node precompute: h = xW+b; a = h@attn_w; p = h@proj(permuted) ----
#define ROWS_K1 16
__global__ __launch_bounds__(256) void k_node(const float* __restrict__ x,
                                              const float* __restrict__ Ww,
                                              const float* __restrict__ Wb,
                                              const float* __restrict__ aw,
                                              const float* __restrict__ pw) {
    __shared__ float xs[ROWS_K1][C];
    __shared__ float hs[ROWS_K1][C];
    const int base = blockIdx.x * ROWS_K1;
    const int t = threadIdx.x;

    // stage 16 x-rows
#pragma unroll
    for (int k = 0; k < 4; k++) {
        int idx = t + k * 256;
        xs[idx >> 6][idx & 63] = x[(base + (idx >> 6)) * C + (idx & 63)];
    }
    __syncthreads();

    // phase 1: h rows (4 rows per thread, one column each)
    {
        int j = t & 63;
        int r0 = (t >> 6) * 4;
        float a0 = 0.f, a1 = 0.f, a2 = 0.f, a3 = 0.f;
#pragma unroll 8
        for (int c = 0; c < C; c++) {
            float w = __ldg(&Ww[c * C + j]);
            a0 = fmaf(xs[r0 + 0][c], w, a0);
            a1 = fmaf(xs[r0 + 1][c], w, a1);
            a2 = fmaf(xs[r0 + 2][c], w, a2);
            a3 = fmaf(xs[r0 + 3][c], w, a3);
        }
        float b = __ldg(&Wb[j]);
        hs[r0 + 0][j] = a0 + b;
        hs[r0 + 1][j] = a1 + b;
        hs[r0 + 2][j] = a2 + b;
        hs[r0 + 3][j] = a3 + b;
    }
    __syncthreads();

    // phase 2: a_src/a_dst (128 outputs)
    if (t < 128) {
        int r = t >> 3, k = t & 7;
        int hh = k & 3;
        int off = (k < 4) ? 0 : C;   // src rows [0,64), dst rows [64,128)
        float acc = 0.f;
#pragma unroll 8
        for (int c = 0; c < C; c++)
            acc = fmaf(hs[r][c], __ldg(&aw[(off + c) * H + hh]), acc);
        g_a[(base + r) * 8 + k] = acc;
    }

    // phase 3: p[n, q] for q = hh*64+j  (4 rows x 4 cols per thread)
    {
        int q0 = (t & 63) * 4;
        int r0 = (t >> 6) * 4;
        int hh = q0 >> 6;
        int j  = q0 & 63;
        float4 A0 = {0,0,0,0}, A1 = {0,0,0,0}, A2 = {0,0,0,0}, A3 = {0,0,0,0};
#pragma unroll 4
        for (int c = 0; c < C; c++) {
            float4 w = __ldg((const float4*)&pw[(c * H + hh) * C + j]);
            float h0 = hs[r0 + 0][c], h1 = hs[r0 + 1][c];
            float h2 = hs[r0 + 2][c], h3 = hs[r0 + 3][c];
            A0.x = fmaf(h0, w.x, A0.x); A0.y = fmaf(h0, w.y, A0.y);
            A0.z = fmaf(h0, w.z, A0.z); A0.w = fmaf(h0, w.w, A0.w);
            A1.x = fmaf(h1, w.x, A1.x); A1.y = fmaf(h1, w.y, A1.y);
            A1.z = fmaf(h1, w.z, A1.z); A1.w = fmaf(h1, w.w, A1.w);
            A2.x = fmaf(h2, w.x, A2.x); A2.y = fmaf(h2, w.y, A2.y);
            A2.z = fmaf(h2, w.z, A2.z); A2.w = fmaf(h2, w.w, A2.w);
            A3.x = fmaf(h3, w.x, A3.x); A3.y = fmaf(h3, w.y, A3.y);
            A3.z = fmaf(h3, w.z, A3.z); A3.w = fmaf(h3, w.w, A3.w);
        }
        *(float4*)&g_p[(base + r0 + 0) * 256 + q0] = A0;
        *(float4*)&g_p[(base + r0 + 1) * 256 + q0] = A1;
        *(float4*)&g_p[(base + r0 + 2) * 256 + q0] = A2;
        *(float4*)&g_p[(base + r0 + 3) * 256 + q0] = A3;
    }
}

// ---- edge pass 1: scores + segment max ----
__global__ __launch_bounds__(256) void k_edge1(const void* __restrict__ ei,
                                               const float* __restrict__ et,
                                               const int* __restrict__ ct,
                                               const float* __restrict__ ab,
                                               const float* __restrict__ dr) {
    int e = blockIdx.x * blockDim.x + threadIdx.x;
    if (e >= NE) return;
    int src = edge_idx(ei, e);
    int dst = edge_idx(ei, (long long)NE + e);

    float lam = log1pf(__expf(dr[0]));              // softplus
    float dt = (float)ct[0] - et[e];
    float decay = __expf(-lam * dt);

    float4 as = *(const float4*)&g_a[src * 8];
    float4 ad = *(const float4*)&g_a[dst * 8 + 4];
    float s[4];
    s[0] = as.x + ad.x + __ldg(&ab[0]);
    s[1] = as.y + ad.y + __ldg(&ab[1]);
    s[2] = as.z + ad.z + __ldg(&ab[2]);
    s[3] = as.w + ad.w + __ldg(&ab[3]);
#pragma unroll
    for (int h = 0; h < 4; h++) {
        float l = s[h];
        l = (l > 0.f) ? l : 0.2f * l;               // LeakyReLU(0.2)
        l *= decay;
        s[h] = l;
        atomicMax(&g_smax[dst * 4 + h], fmap(l));
    }
    *(float4*)&g_scores[e * 4] = make_float4(s[0], s[1], s[2], s[3]);
}

// ---- edge pass 2: exp(score - max), segment sum ----
__global__ __launch_bounds__(256) void k_edge2(const void* __restrict__ ei) {
    int e = blockIdx.x * blockDim.x + threadIdx.x;
    if (e >= NE) return;
    int dst = edge_idx(ei, (long long)NE + e);
    float4 s = *(const float4*)&g_scores[e * 4];
    uint4 m = *(const uint4*)&g_smax[dst * 4];
    float e0 = __expf(s.x - funmap(m.x));
    float e1 = __expf(s.y - funmap(m.y));
    float e2 = __expf(s.z - funmap(m.z));
    float e3 = __expf(s.w - funmap(m.w));
    *(float4*)&g_scores[e * 4] = make_float4(e0, e1, e2, e3);
    atomicAdd(&g_ssum[dst * 4 + 0], e0);
    atomicAdd(&g_ssum[dst * 4 + 1], e1);
    atomicAdd(&g_ssum[dst * 4 + 2], e2);
    atomicAdd(&g_ssum[dst * 4 + 3], e3);
}

// ---- edge pass 3: warp per edge, gather p[src], scatter attn-weighted sum ----
__global__ __launch_bounds__(256) void k_edge3(const void* __restrict__ ei) {
    int e = blockIdx.x * 8 + (threadIdx.x >> 5);
    if (e >= NE) return;
    int lane = threadIdx.x & 31;
    int src = edge_idx(ei, e);
    int dst = edge_idx(ei, (long long)NE + e);

    float4 ev = *(const float4*)&g_scores[e * 4];
    float4 sv = *(const float4*)&g_ssum[dst * 4];
    float a0 = ev.x / (sv.x + 1e-8f);
    float a1 = ev.y / (sv.y + 1e-8f);
    float a2 = ev.z / (sv.z + 1e-8f);
    float a3 = ev.w / (sv.w + 1e-8f);

    const float* pr = &g_p[src * 256];
    float acc0 = a0 * pr[lane]       + a1 * pr[64 + lane]
               + a2 * pr[128 + lane] + a3 * pr[192 + lane];
    float acc1 = a0 * pr[32 + lane]  + a1 * pr[96 + lane]
               + a2 * pr[160 + lane] + a3 * pr[224 + lane];
    atomicAdd(&g_agg[dst * 64 + lane], acc0);
    atomicAdd(&g_agg[dst * 64 + 32 + lane], acc1);
}

// ---- final: bias + residual + LayerNorm + ReLU (warp per node) ----
__global__ __launch_bounds__(256) void k_final(const float* __restrict__ x,
                                               const float* __restrict__ pb,
                                               const float* __restrict__ lg,
                                               const float* __restrict__ lb,
                                               float* __restrict__ out) {
    int n = blockIdx.x * 8 + (threadIdx.x >> 5);
    if (n >= NN) return;
    int lane = threadIdx.x & 31;
    float z0 = g_agg[n * 64 + lane]      + __ldg(&pb[lane])      + x[n * 64 + lane];
    float z1 = g_agg[n * 64 + 32 + lane] + __ldg(&pb[32 + lane]) + x[n * 64 + 32 + lane];
    float s = z0 + z1;
#pragma unroll
    for (int o = 16; o; o >>= 1) s += __shfl_xor_sync(0xffffffffu, s, o);
    float mu = s * (1.f / 64.f);
    float d0 = z0 - mu, d1 = z1 - mu;
    float v = d0 * d0 + d1 * d1;
#pragma unroll
    for (int o = 16; o; o >>= 1) v += __shfl_xor_sync(0xffffffffu, v, o);
    float inv = rsqrtf(v * (1.f / 64.f) + 1e-5f);
    float y0 = __ldg(&lg[lane])      * d0 * inv + __ldg(&lb[lane]);
    float y1 = __ldg(&lg[32 + lane]) * d1 * inv + __ldg(&lb[32 + lane]);
    out[n * 64 + lane]      = fmaxf(y0, 0.f);
    out[n * 64 + 32 + lane] = fmaxf(y1, 0.f);
}

extern "C" void kernel_launch(void* const* d_in, const int* in_sizes, int n_in,
                              void* d_out, int out_size) {
    const float* x  = (const float*)d_in[0];
    const void*  ei = d_in[1];                 // int64 or int32, probed on device
    const float* et = (const float*)d_in[2];
    const int*   ct = (const int*)d_in[3];
    const float* Ww = (const float*)d_in[4];
    const float* Wb = (const float*)d_in[5];
    const float* aw = (const float*)d_in[6];
    const float* ab = (const float*)d_in[7];
    const float* dr = (const float*)d_in[8];
    const float* pw = (const float*)d_in[9];
    const float* pb = (const float*)d_in[10];
    const float* lg = (const float*)d_in[11];
    const float* lb = (const float*)d_in[12];
    float* out = (float*)d_out;

    k_detect<<<1, 1>>>(ei);
    k_init<<<25000, 256>>>();
    k_node<<<NN / ROWS_K1, 256>>>(x, Ww, Wb, aw, pw);
    k_edge1<<<NE / 256, 256>>>(ei, et, ct, ab, dr);
    k_edge2<<<NE / 256, 256>>>(ei);
    k_edge3<<<NE / 8, 256>>>(ei);
    k_final<<<NN / 8, 256>>>(x, pb, lg, lb, out);
}

// round 4
// speedup vs baseline: 1.4027x; 1.4027x over previous
#include <cuda_runtime.h>

#define NN 100000
#define NE 800000
#define C 64
#define H 4
#define NB_SCAN 98   // ceil(NN/1024)

// ---- scratch (allocation-free: __device__ globals) ----
__device__ float g_h[NN * C];         // h = xW + b
__device__ float g_a[NN * 8];         // a_src[0..3], a_dst[0..3]
__device__ int   g_cnt[NN];           // in-degree histogram
__device__ int   g_off[NN + 1];       // CSR offsets
__device__ int   g_cur[NN];           // scatter cursors
__device__ int   g_btot[NB_SCAN];     // scan block totals
__device__ int   g_csrc[NE];          // CSR: src per slot
__device__ float g_ce[NE * 4];        // CSR: exp-scores per slot (float4)
__device__ float g_u[NN * 256];       // normalized per-node aggregate, q = h*64+c
__device__ int   g_idx64;

__device__ __forceinline__ int edge_idx(const void* ei, long long pos) {
    if (g_idx64) return (int)((const long long*)ei)[pos];
    return ((const int*)ei)[pos];
}

__global__ void k_detect(const void* ei) {
    const long long* p = (const long long*)ei;
    bool ok = true;
    for (int i = 0; i < 4; i++) {
        long long v = p[i];
        if (v < 0 || v >= NN) ok = false;
    }
    g_idx64 = ok ? 1 : 0;
}

__global__ void k_zero() {
    int i = blockIdx.x * blockDim.x + threadIdx.x;
    if (i < NN) g_cnt[i] = 0;
}

// ---- node precompute: h = xW+b ; a = h @ attn_w ----
#define ROWS_K1 16
__global__ __launch_bounds__(256) void k_node(const float* __restrict__ x,
                                              const float* __restrict__ Ww,
                                              const float* __restrict__ Wb,
                                              const float* __restrict__ aw) {
    __shared__ float xs[ROWS_K1][C];
    __shared__ float hs[ROWS_K1][C];
    const int base = blockIdx.x * ROWS_K1;
    const int t = threadIdx.x;

#pragma unroll
    for (int k = 0; k < 4; k++) {
        int idx = t + k * 256;
        xs[idx >> 6][idx & 63] = x[(base + (idx >> 6)) * C + (idx & 63)];
    }
    __syncthreads();

    {
        int j = t & 63;
        int r0 = (t >> 6) * 4;
        float a0 = 0.f, a1 = 0.f, a2 = 0.f, a3 = 0.f;
#pragma unroll 8
        for (int c = 0; c < C; c++) {
            float w = __ldg(&Ww[c * C + j]);
            a0 = fmaf(xs[r0 + 0][c], w, a0);
            a1 = fmaf(xs[r0 + 1][c], w, a1);
            a2 = fmaf(xs[r0 + 2][c], w, a2);
            a3 = fmaf(xs[r0 + 3][c], w, a3);
        }
        float b = __ldg(&Wb[j]);
        a0 += b; a1 += b; a2 += b; a3 += b;
        hs[r0 + 0][j] = a0; hs[r0 + 1][j] = a1;
        hs[r0 + 2][j] = a2; hs[r0 + 3][j] = a3;
        g_h[(base + r0 + 0) * C + j] = a0;
        g_h[(base + r0 + 1) * C + j] = a1;
        g_h[(base + r0 + 2) * C + j] = a2;
        g_h[(base + r0 + 3) * C + j] = a3;
    }
    __syncthreads();

    if (t < 128) {
        int r = t >> 3, k = t & 7;
        int hh = k & 3;
        int off = (k < 4) ? 0 : C;
        float acc = 0.f;
#pragma unroll 8
        for (int c = 0; c < C; c++)
            acc = fmaf(hs[r][c], __ldg(&aw[(off + c) * H + hh]), acc);
        g_a[(base + r) * 8 + k] = acc;
    }
}

// ---- in-degree histogram ----
__global__ __launch_bounds__(256) void k_hist(const void* __restrict__ ei) {
    int e = blockIdx.x * blockDim.x + threadIdx.x;
    if (e >= NE) return;
    int dst = edge_idx(ei, (long long)NE + e);
    atomicAdd(&g_cnt[dst], 1);
}

// ---- scan phase A: per-1024-chunk exclusive scan ----
__global__ __launch_bounds__(1024) void k_scanA() {
    __shared__ int sh[1024];
    int b = blockIdx.x, t = threadIdx.x;
    int idx = b * 1024 + t;
    int v = (idx < NN) ? g_cnt[idx] : 0;
    sh[t] = v;
    __syncthreads();
#pragma unroll
    for (int o = 1; o < 1024; o <<= 1) {
        int x = (t >= o) ? sh[t - o] : 0;
        __syncthreads();
        sh[t] += x;
        __syncthreads();
    }
    if (idx < NN) g_off[idx] = sh[t] - v;
    if (t == 1023) g_btot[b] = sh[1023];
}

// ---- scan phase B: add chunk prefixes, init cursors ----
__global__ __launch_bounds__(1024) void k_scanB() {
    __shared__ int bt[NB_SCAN];
    int b = blockIdx.x, t = threadIdx.x;
    if (t < NB_SCAN) bt[t] = g_btot[t];
    __syncthreads();
    int s = 0;
    for (int i = 0; i < b; i++) s += bt[i];
    int idx = b * 1024 + t;
    if (idx < NN) {
        int o = g_off[idx] + s;
        g_off[idx] = o;
        g_cur[idx] = o;
    }
    if (b == 0 && t == 0) g_off[NN] = NE;
}

// ---- fused score + CSR scatter (no max pass: scores bounded, exp safe) ----
__global__ __launch_bounds__(256) void k_scatter(const void* __restrict__ ei,
                                                 const float* __restrict__ et,
                                                 const int* __restrict__ ct,
                                                 const float* __restrict__ ab,
                                                 const float* __restrict__ dr) {
    int e = blockIdx.x * blockDim.x + threadIdx.x;
    if (e >= NE) return;
    int src = edge_idx(ei, e);
    int dst = edge_idx(ei, (long long)NE + e);

    float lam = log1pf(__expf(dr[0]));            // softplus
    float dt = (float)ct[0] - et[e];
    float decay = __expf(-lam * dt);

    float4 as = *(const float4*)&g_a[src * 8];
    float4 ad = *(const float4*)&g_a[dst * 8 + 4];
    float s[4];
    s[0] = as.x + ad.x + __ldg(&ab[0]);
    s[1] = as.y + ad.y + __ldg(&ab[1]);
    s[2] = as.z + ad.z + __ldg(&ab[2]);
    s[3] = as.w + ad.w + __ldg(&ab[3]);
#pragma unroll
    for (int h = 0; h < 4; h++) {
        float l = s[h];
        l = (l > 0.f) ? l : 0.2f * l;             // LeakyReLU(0.2)
        s[h] = __expf(l * decay);
    }
    int pos = atomicAdd(&g_cur[dst], 1);
    g_csrc[pos] = src;
    *(float4*)&g_ce[pos * 4] = make_float4(s[0], s[1], s[2], s[3]);
}

// ---- aggregation: warp per dst, zero atomics, normalize after sum ----
__global__ __launch_bounds__(256) void k_agg() {
    int n = blockIdx.x * 8 + (threadIdx.x >> 5);
    if (n >= NN) return;
    int lane = threadIdx.x & 31;
    int beg = g_off[n], end = g_off[n + 1];

    float a00 = 0.f, a01 = 0.f, a10 = 0.f, a11 = 0.f;
    float a20 = 0.f, a21 = 0.f, a30 = 0.f, a31 = 0.f;
    float s0 = 0.f, s1 = 0.f, s2 = 0.f, s3 = 0.f;

    for (int i = beg; i < end; i++) {
        int src = __ldg(&g_csrc[i]);
        float4 ev = __ldg((const float4*)&g_ce[i * 4]);
        float h0 = __ldg(&g_h[src * C + lane]);
        float h1 = __ldg(&g_h[src * C + 32 + lane]);
        a00 = fmaf(ev.x, h0, a00); a01 = fmaf(ev.x, h1, a01);
        a10 = fmaf(ev.y, h0, a10); a11 = fmaf(ev.y, h1, a11);
        a20 = fmaf(ev.z, h0, a20); a21 = fmaf(ev.z, h1, a21);
        a30 = fmaf(ev.w, h0, a30); a31 = fmaf(ev.w, h1, a31);
        s0 += ev.x; s1 += ev.y; s2 += ev.z; s3 += ev.w;
    }
    float r0 = 1.f / (s0 + 1e-8f);
    float r1 = 1.f / (s1 + 1e-8f);
    float r2 = 1.f / (s2 + 1e-8f);
    float r3 = 1.f / (s3 + 1e-8f);

    float* u = &g_u[n * 256];
    u[0 * 64 + lane]      = a00 * r0;  u[0 * 64 + 32 + lane] = a01 * r0;
    u[1 * 64 + lane]      = a10 * r1;  u[1 * 64 + 32 + lane] = a11 * r1;
    u[2 * 64 + lane]      = a20 * r2;  u[2 * 64 + 32 + lane] = a21 * r2;
    u[3 * 64 + lane]      = a30 * r3;  u[3 * 64 + 32 + lane] = a31 * r3;
}

// ---- GEMM u(NNx256) @ W2(256x64) + bias + residual + LN + ReLU ----
// W2[q=h*64+c][j] = proj_w[(c*4+h)*64 + j]
__global__ __launch_bounds__(256) void k_gemm(const float* __restrict__ pw,
                                              const float* __restrict__ pb,
                                              const float* __restrict__ x,
                                              const float* __restrict__ lg,
                                              const float* __restrict__ lb,
                                              float* __restrict__ out) {
    __shared__ float us[64][68];   // [k][node]
    __shared__ float ws[64][68];   // [k][col]
    const int t = threadIdx.x;
    const int tx = t & 15, ty = t >> 4;
    const int base = blockIdx.x * 64;

    float acc[4][4];
#pragma unroll
    for (int i = 0; i < 4; i++)
#pragma unroll
        for (int j = 0; j < 4; j++) acc[i][j] = 0.f;

    for (int kb = 0; kb < 4; kb++) {   // kb == head index
        // stage W2 chunk: ws[c][j] = pw[(c*4+kb)*64 + j]
#pragma unroll
        for (int r = 0; r < 4; r++) {
            int c = r * 16 + ty;
            float4 w = __ldg((const float4*)&pw[(c * 4 + kb) * 64 + tx * 4]);
            ws[c][tx * 4 + 0] = w.x; ws[c][tx * 4 + 1] = w.y;
            ws[c][tx * 4 + 2] = w.z; ws[c][tx * 4 + 3] = w.w;
        }
        // stage u chunk transposed: us[k][row] = u[base+row][kb*64+k]
#pragma unroll
        for (int r = 0; r < 4; r++) {
            int row = r * 16 + ty;
            int node = base + row;
            float4 v = make_float4(0.f, 0.f, 0.f, 0.f);
            if (node < NN)
                v = *(const float4*)&g_u[node * 256 + kb * 64 + tx * 4];
            us[tx * 4 + 0][row] = v.x; us[tx * 4 + 1][row] = v.y;
            us[tx * 4 + 2][row] = v.z; us[tx * 4 + 3][row] = v.w;
        }
        __syncthreads();

#pragma unroll 8
        for (int k = 0; k < 64; k++) {
            float4 av = *(const float4*)&us[k][ty * 4];
            float4 bv = *(const float4*)&ws[k][tx * 4];
            float a[4] = {av.x, av.y, av.z, av.w};
            float b[4] = {bv.x, bv.y, bv.z, bv.w};
#pragma unroll
            for (int i = 0; i < 4; i++)
#pragma unroll
                for (int j = 0; j < 4; j++)
                    acc[i][j] = fmaf(a[i], b[j], acc[i][j]);
        }
        __syncthreads();
    }

    // epilogue: z = acc + pb + x ; stash to smem (reuse us) for row LN
    float4 bias = __ldg((const float4*)&pb[tx * 4]);
#pragma unroll
    for (int i = 0; i < 4; i++) {
        int node = base + ty * 4 + i;
        float4 xv = make_float4(0.f, 0.f, 0.f, 0.f);
        if (node < NN)
            xv = *(const float4*)&x[node * 64 + tx * 4];
        us[ty * 4 + i][tx * 4 + 0] = acc[i][0] + bias.x + xv.x;
        us[ty * 4 + i][tx * 4 + 1] = acc[i][1] + bias.y + xv.y;
        us[ty * 4 + i][tx * 4 + 2] = acc[i][2] + bias.z + xv.z;
        us[ty * 4 + i][tx * 4 + 3] = acc[i][3] + bias.w + xv.w;
    }
    __syncthreads();

    // LN + ReLU: 8 warps x 8 rows each
    int w = t >> 5, lane = t & 31;
#pragma unroll
    for (int rr = 0; rr < 8; rr++) {
        int row = w * 8 + rr;
        int node = base + row;
        if (node >= NN) break;
        float z0 = us[row][lane];
        float z1 = us[row][32 + lane];
        float s = z0 + z1;
#pragma unroll
        for (int o = 16; o; o >>= 1) s += __shfl_xor_sync(0xffffffffu, s, o);
        float mu = s * (1.f / 64.f);
        float d0 = z0 - mu, d1 = z1 - mu;
        float v = d0 * d0 + d1 * d1;
#pragma unroll
        for (int o = 16; o; o >>= 1) v += __shfl_xor_sync(0xffffffffu, v, o);
        float inv = rsqrtf(v * (1.f / 64.f) + 1e-5f);
        float y0 = __ldg(&lg[lane])      * d0 * inv + __ldg(&lb[lane]);
        float y1 = __ldg(&lg[32 + lane]) * d1 * inv + __ldg(&lb[32 + lane]);
        out[node * 64 + lane]      = fmaxf(y0, 0.f);
        out[node * 64 + 32 + lane] = fmaxf(y1, 0.f);
    }
}

extern "C" void kernel_launch(void* const* d_in, const int* in_sizes, int n_in,
                              void* d_out, int out_size) {
    const float* x  = (const float*)d_in[0];
    const void*  ei = d_in[1];
    const float* et = (const float*)d_in[2];
    const int*   ct = (const int*)d_in[3];
    const float* Ww = (const float*)d_in[4];
    const float* Wb = (const float*)d_in[5];
    const float* aw = (const float*)d_in[6];
    const float* ab = (const float*)d_in[7];
    const float* dr = (const float*)d_in[8];
    const float* pw = (const float*)d_in[9];
    const float* pb = (const float*)d_in[10];
    const float* lg = (const float*)d_in[11];
    const float* lb = (const float*)d_in[12];
    float* out = (float*)d_out;

    k_detect<<<1, 1>>>(ei);
    k_zero<<<(NN + 255) / 256, 256>>>();
    k_node<<<NN / ROWS_K1, 256>>>(x, Ww, Wb, aw);
    k_hist<<<NE / 256, 256>>>(ei);
    k_scanA<<<NB_SCAN, 1024>>>();
    k_scanB<<<NB_SCAN, 1024>>>();
    k_scatter<<<NE / 256, 256>>>(ei, et, ct, ab, dr);
    k_agg<<<NN / 8, 256>>>();
    k_gemm<<<(NN + 63) / 64, 256>>>(pw, pb, x, lg, lb, out);
}

// round 5
// speedup vs baseline: 1.4217x; 1.0135x over previous
#include <cuda_runtime.h>

#define NN 100000
#define NE 800000
#define C 64
#define H 4
#define NB_SCAN 98   // ceil(NN/1024)

// ---- scratch (allocation-free: __device__ globals) ----
__device__ float g_h[NN * C];         // h = xW + b
__device__ float g_a[NN * 8];         // a_src[0..3], a_dst[0..3]
__device__ int   g_cnt[NN];           // in-degree histogram
__device__ int   g_off[NN + 1];       // CSR offsets
__device__ int   g_cur[NN];           // scatter cursors
__device__ int   g_btot[NB_SCAN];     // scan block totals
__device__ int   g_csrc[NE];          // CSR: src per slot
__device__ float g_ce[NE * 4];        // CSR: exp-scores per slot (float4)
__device__ int   g_idx64;

__device__ __forceinline__ int edge_idx(const void* ei, long long pos) {
    if (g_idx64) return (int)((const long long*)ei)[pos];
    return ((const int*)ei)[pos];
}

// ---- fused: dtype probe + zero histogram ----
__global__ void k_init(const void* ei) {
    int i = blockIdx.x * blockDim.x + threadIdx.x;
    if (i < NN) g_cnt[i] = 0;
    if (i == 0) {
        const long long* p = (const long long*)ei;
        bool ok = true;
        for (int k = 0; k < 4; k++) {
            long long v = p[k];
            if (v < 0 || v >= NN) ok = false;
        }
        g_idx64 = ok ? 1 : 0;
    }
}

// ---- node precompute: h = xW+b ; a = h @ attn_w ----
#define ROWS_K1 16
__global__ __launch_bounds__(256) void k_node(const float* __restrict__ x,
                                              const float* __restrict__ Ww,
                                              const float* __restrict__ Wb,
                                              const float* __restrict__ aw) {
    __shared__ float xs[ROWS_K1][C];
    __shared__ float hs[ROWS_K1][C];
    const int base = blockIdx.x * ROWS_K1;
    const int t = threadIdx.x;

#pragma unroll
    for (int k = 0; k < 4; k++) {
        int idx = t + k * 256;
        xs[idx >> 6][idx & 63] = x[(base + (idx >> 6)) * C + (idx & 63)];
    }
    __syncthreads();

    {
        int j = t & 63;
        int r0 = (t >> 6) * 4;
        float a0 = 0.f, a1 = 0.f, a2 = 0.f, a3 = 0.f;
#pragma unroll 8
        for (int c = 0; c < C; c++) {
            float w = __ldg(&Ww[c * C + j]);
            a0 = fmaf(xs[r0 + 0][c], w, a0);
            a1 = fmaf(xs[r0 + 1][c], w, a1);
            a2 = fmaf(xs[r0 + 2][c], w, a2);
            a3 = fmaf(xs[r0 + 3][c], w, a3);
        }
        float b = __ldg(&Wb[j]);
        a0 += b; a1 += b; a2 += b; a3 += b;
        hs[r0 + 0][j] = a0; hs[r0 + 1][j] = a1;
        hs[r0 + 2][j] = a2; hs[r0 + 3][j] = a3;
        g_h[(base + r0 + 0) * C + j] = a0;
        g_h[(base + r0 + 1) * C + j] = a1;
        g_h[(base + r0 + 2) * C + j] = a2;
        g_h[(base + r0 + 3) * C + j] = a3;
    }
    __syncthreads();

    if (t < 128) {
        int r = t >> 3, k = t & 7;
        int hh = k & 3;
        int off = (k < 4) ? 0 : C;
        float acc = 0.f;
#pragma unroll 8
        for (int c = 0; c < C; c++)
            acc = fmaf(hs[r][c], __ldg(&aw[(off + c) * H + hh]), acc);
        g_a[(base + r) * 8 + k] = acc;
    }
}

// ---- in-degree histogram ----
__global__ __launch_bounds__(256) void k_hist(const void* __restrict__ ei) {
    int e = blockIdx.x * blockDim.x + threadIdx.x;
    if (e >= NE) return;
    int dst = edge_idx(ei, (long long)NE + e);
    atomicAdd(&g_cnt[dst], 1);
}

// ---- scan phase A: per-1024-chunk exclusive scan ----
__global__ __launch_bounds__(1024) void k_scanA() {
    __shared__ int sh[1024];
    int b = blockIdx.x, t = threadIdx.x;
    int idx = b * 1024 + t;
    int v = (idx < NN) ? g_cnt[idx] : 0;
    sh[t] = v;
    __syncthreads();
#pragma unroll
    for (int o = 1; o < 1024; o <<= 1) {
        int x = (t >= o) ? sh[t - o] : 0;
        __syncthreads();
        sh[t] += x;
        __syncthreads();
    }
    if (idx < NN) g_off[idx] = sh[t] - v;
    if (t == 1023) g_btot[b] = sh[1023];
}

// ---- scan phase B: add chunk prefixes, init cursors ----
__global__ __launch_bounds__(1024) void k_scanB() {
    __shared__ int bt[NB_SCAN];
    int b = blockIdx.x, t = threadIdx.x;
    if (t < NB_SCAN) bt[t] = g_btot[t];
    __syncthreads();
    int s = 0;
    for (int i = 0; i < b; i++) s += bt[i];
    int idx = b * 1024 + t;
    if (idx < NN) {
        int o = g_off[idx] + s;
        g_off[idx] = o;
        g_cur[idx] = o;
    }
    if (b == 0 && t == 0) g_off[NN] = NE;
}

// ---- fused score + CSR scatter ----
__global__ __launch_bounds__(256) void k_scatter(const void* __restrict__ ei,
                                                 const float* __restrict__ et,
                                                 const int* __restrict__ ct,
                                                 const float* __restrict__ ab,
                                                 const float* __restrict__ dr) {
    int e = blockIdx.x * blockDim.x + threadIdx.x;
    if (e >= NE) return;
    int src = edge_idx(ei, e);
    int dst = edge_idx(ei, (long long)NE + e);

    float lam = log1pf(__expf(dr[0]));            // softplus
    float dt = (float)ct[0] - et[e];
    float decay = __expf(-lam * dt);

    float4 as = *(const float4*)&g_a[src * 8];
    float4 ad = *(const float4*)&g_a[dst * 8 + 4];
    float s[4];
    s[0] = as.x + ad.x + __ldg(&ab[0]);
    s[1] = as.y + ad.y + __ldg(&ab[1]);
    s[2] = as.z + ad.z + __ldg(&ab[2]);
    s[3] = as.w + ad.w + __ldg(&ab[3]);
#pragma unroll
    for (int h = 0; h < 4; h++) {
        float l = s[h];
        l = (l > 0.f) ? l : 0.2f * l;             // LeakyReLU(0.2)
        s[h] = __expf(l * decay);
    }
    int pos = atomicAdd(&g_cur[dst], 1);
    g_csrc[pos] = src;
    *(float4*)&g_ce[pos * 4] = make_float4(s[0], s[1], s[2], s[3]);
}

// ---- FUSED aggregation + projection GEMM + bias/residual/LN/ReLU ----
// 32 nodes per block (100000 % 32 == 0). Agg phase: 8 warps x 4 nodes,
// normalized aggregate u written straight to smem (node-major, pad 260).
// GEMM phase: 32x64 output, K=256 from smem, k-chunked weights.
#define TB 32
#define UPAD 260
__global__ __launch_bounds__(256) void k_aggemm(const float* __restrict__ pw,
                                                const float* __restrict__ pb,
                                                const float* __restrict__ x,
                                                const float* __restrict__ lg,
                                                const float* __restrict__ lb,
                                                float* __restrict__ out) {
    __shared__ float us[TB][UPAD];   // u[node_local][q], q = h*64+c
    __shared__ float ws[32][68];     // W2 chunk [kk][j], reused as z in epilogue
    const int t = threadIdx.x;
    const int w = t >> 5, lane = t & 31;
    const int base = blockIdx.x * TB;

    // ---- phase 1: CSR aggregation, 4 nodes per warp ----
#pragma unroll
    for (int rr = 0; rr < 4; rr++) {
        int r = w * 4 + rr;
        int n = base + r;
        int i = g_off[n], end = g_off[n + 1];

        float a00 = 0.f, a01 = 0.f, a10 = 0.f, a11 = 0.f;
        float a20 = 0.f, a21 = 0.f, a30 = 0.f, a31 = 0.f;
        float s0 = 0.f, s1 = 0.f, s2 = 0.f, s3 = 0.f;

        for (; i + 2 <= end; i += 2) {
            int sa = __ldg(&g_csrc[i]);
            int sb = __ldg(&g_csrc[i + 1]);
            float4 ea = __ldg((const float4*)&g_ce[i * 4]);
            float4 eb = __ldg((const float4*)&g_ce[i * 4 + 4]);
            float ha0 = __ldg(&g_h[sa * C + lane]);
            float ha1 = __ldg(&g_h[sa * C + 32 + lane]);
            float hb0 = __ldg(&g_h[sb * C + lane]);
            float hb1 = __ldg(&g_h[sb * C + 32 + lane]);
            a00 = fmaf(ea.x, ha0, a00); a01 = fmaf(ea.x, ha1, a01);
            a10 = fmaf(ea.y, ha0, a10); a11 = fmaf(ea.y, ha1, a11);
            a20 = fmaf(ea.z, ha0, a20); a21 = fmaf(ea.z, ha1, a21);
            a30 = fmaf(ea.w, ha0, a30); a31 = fmaf(ea.w, ha1, a31);
            s0 += ea.x; s1 += ea.y; s2 += ea.z; s3 += ea.w;
            a00 = fmaf(eb.x, hb0, a00); a01 = fmaf(eb.x, hb1, a01);
            a10 = fmaf(eb.y, hb0, a10); a11 = fmaf(eb.y, hb1, a11);
            a20 = fmaf(eb.z, hb0, a20); a21 = fmaf(eb.z, hb1, a21);
            a30 = fmaf(eb.w, hb0, a30); a31 = fmaf(eb.w, hb1, a31);
            s0 += eb.x; s1 += eb.y; s2 += eb.z; s3 += eb.w;
        }
        if (i < end) {
            int sa = __ldg(&g_csrc[i]);
            float4 ea = __ldg((const float4*)&g_ce[i * 4]);
            float ha0 = __ldg(&g_h[sa * C + lane]);
            float ha1 = __ldg(&g_h[sa * C + 32 + lane]);
            a00 = fmaf(ea.x, ha0, a00); a01 = fmaf(ea.x, ha1, a01);
            a10 = fmaf(ea.y, ha0, a10); a11 = fmaf(ea.y, ha1, a11);
            a20 = fmaf(ea.z, ha0, a20); a21 = fmaf(ea.z, ha1, a21);
            a30 = fmaf(ea.w, ha0, a30); a31 = fmaf(ea.w, ha1, a31);
            s0 += ea.x; s1 += ea.y; s2 += ea.z; s3 += ea.w;
        }
        float r0 = 1.f / (s0 + 1e-8f);
        float r1 = 1.f / (s1 + 1e-8f);
        float r2 = 1.f / (s2 + 1e-8f);
        float r3 = 1.f / (s3 + 1e-8f);
        us[r][0 * 64 + lane] = a00 * r0;  us[r][0 * 64 + 32 + lane] = a01 * r0;
        us[r][1 * 64 + lane] = a10 * r1;  us[r][1 * 64 + 32 + lane] = a11 * r1;
        us[r][2 * 64 + lane] = a20 * r2;  us[r][2 * 64 + 32 + lane] = a21 * r2;
        us[r][3 * 64 + lane] = a30 * r3;  us[r][3 * 64 + 32 + lane] = a31 * r3;
    }
    __syncthreads();

    // ---- phase 2: GEMM 32x64, K = 256 in chunks of 32 ----
    const int tx = t & 15, ty = t >> 4;   // cols tx*4, rows ty*2
    float acc[2][4];
#pragma unroll
    for (int i = 0; i < 2; i++)
#pragma unroll
        for (int j = 0; j < 4; j++) acc[i][j] = 0.f;

    for (int kc = 0; kc < 8; kc++) {
        // stage W2 chunk: ws[kk][j] = pw[((q&63)*4 + (q>>6))*64 + j], q = kc*32+kk
#pragma unroll
        for (int rr = 0; rr < 2; rr++) {
            int kk = ty * 2 + rr;
            int q = kc * 32 + kk;
            int row = ((q & 63) << 2) + (q >> 6);
            float4 wv = __ldg((const float4*)&pw[row * 64 + tx * 4]);
            ws[kk][tx * 4 + 0] = wv.x; ws[kk][tx * 4 + 1] = wv.y;
            ws[kk][tx * 4 + 2] = wv.z; ws[kk][tx * 4 + 3] = wv.w;
        }
        __syncthreads();

#pragma unroll 8
        for (int k4 = 0; k4 < 8; k4++) {
            float4 a0 = *(const float4*)&us[ty * 2 + 0][kc * 32 + k4 * 4];
            float4 a1 = *(const float4*)&us[ty * 2 + 1][kc * 32 + k4 * 4];
            float4 b0 = *(const float4*)&ws[k4 * 4 + 0][tx * 4];
            float4 b1 = *(const float4*)&ws[k4 * 4 + 1][tx * 4];
            float4 b2 = *(const float4*)&ws[k4 * 4 + 2][tx * 4];
            float4 b3 = *(const float4*)&ws[k4 * 4 + 3][tx * 4];
            acc[0][0] = fmaf(a0.x, b0.x, acc[0][0]); acc[0][1] = fmaf(a0.x, b0.y, acc[0][1]);
            acc[0][2] = fmaf(a0.x, b0.z, acc[0][2]); acc[0][3] = fmaf(a0.x, b0.w, acc[0][3]);
            acc[1][0] = fmaf(a1.x, b0.x, acc[1][0]); acc[1][1] = fmaf(a1.x, b0.y, acc[1][1]);
            acc[1][2] = fmaf(a1.x, b0.z, acc[1][2]); acc[1][3] = fmaf(a1.x, b0.w, acc[1][3]);
            acc[0][0] = fmaf(a0.y, b1.x, acc[0][0]); acc[0][1] = fmaf(a0.y, b1.y, acc[0][1]);
            acc[0][2] = fmaf(a0.y, b1.z, acc[0][2]); acc[0][3] = fmaf(a0.y, b1.w, acc[0][3]);
            acc[1][0] = fmaf(a1.y, b1.x, acc[1][0]); acc[1][1] = fmaf(a1.y, b1.y, acc[1][1]);
            acc[1][2] = fmaf(a1.y, b1.z, acc[1][2]); acc[1][3] = fmaf(a1.y, b1.w, acc[1][3]);
            acc[0][0] = fmaf(a0.z, b2.x, acc[0][0]); acc[0][1] = fmaf(a0.z, b2.y, acc[0][1]);
            acc[0][2] = fmaf(a0.z, b2.z, acc[0][2]); acc[0][3] = fmaf(a0.z, b2.w, acc[0][3]);
            acc[1][0] = fmaf(a1.z, b2.x, acc[1][0]); acc[1][1] = fmaf(a1.z, b2.y, acc[1][1]);
            acc[1][2] = fmaf(a1.z, b2.z, acc[1][2]); acc[1][3] = fmaf(a1.z, b2.w, acc[1][3]);
            acc[0][0] = fmaf(a0.w, b3.x, acc[0][0]); acc[0][1] = fmaf(a0.w, b3.y, acc[0][1]);
            acc[0][2] = fmaf(a0.w, b3.z, acc[0][2]); acc[0][3] = fmaf(a0.w, b3.w, acc[0][3]);
            acc[1][0] = fmaf(a1.w, b3.x, acc[1][0]); acc[1][1] = fmaf(a1.w, b3.y, acc[1][1]);
            acc[1][2] = fmaf(a1.w, b3.z, acc[1][2]); acc[1][3] = fmaf(a1.w, b3.w, acc[1][3]);
        }
        __syncthreads();
    }

    // ---- epilogue: z = acc + pb + x into ws, then LN + ReLU ----
    float4 bias = __ldg((const float4*)&pb[tx * 4]);
#pragma unroll
    for (int i = 0; i < 2; i++) {
        int node = base + ty * 2 + i;
        float4 xv = *(const float4*)&x[node * 64 + tx * 4];
        ws[ty * 2 + i][tx * 4 + 0] = acc[i][0] + bias.x + xv.x;
        ws[ty * 2 + i][tx * 4 + 1] = acc[i][1] + bias.y + xv.y;
        ws[ty * 2 + i][tx * 4 + 2] = acc[i][2] + bias.z + xv.z;
        ws[ty * 2 + i][tx * 4 + 3] = acc[i][3] + bias.w + xv.w;
    }
    __syncthreads();

#pragma unroll
    for (int rr = 0; rr < 4; rr++) {
        int row = w * 4 + rr;
        int node = base + row;
        float z0 = ws[row][lane];
        float z1 = ws[row][32 + lane];
        float s = z0 + z1;
#pragma unroll
        for (int o = 16; o; o >>= 1) s += __shfl_xor_sync(0xffffffffu, s, o);
        float mu = s * (1.f / 64.f);
        float d0 = z0 - mu, d1 = z1 - mu;
        float v = d0 * d0 + d1 * d1;
#pragma unroll
        for (int o = 16; o; o >>= 1) v += __shfl_xor_sync(0xffffffffu, v, o);
        float inv = rsqrtf(v * (1.f / 64.f) + 1e-5f);
        float y0 = __ldg(&lg[lane])      * d0 * inv + __ldg(&lb[lane]);
        float y1 = __ldg(&lg[32 + lane]) * d1 * inv + __ldg(&lb[32 + lane]);
        out[node * 64 + lane]      = fmaxf(y0, 0.f);
        out[node * 64 + 32 + lane] = fmaxf(y1, 0.f);
    }
}

extern "C" void kernel_launch(void* const* d_in, const int* in_sizes, int n_in,
                              void* d_out, int out_size) {
    const float* x  = (const float*)d_in[0];
    const void*  ei = d_in[1];
    const float* et = (const float*)d_in[2];
    const int*   ct = (const int*)d_in[3];
    const float* Ww = (const float*)d_in[4];
    const float* Wb = (const float*)d_in[5];
    const float* aw = (const float*)d_in[6];
    const float* ab = (const float*)d_in[7];
    const float* dr = (const float*)d_in[8];
    const float* pw = (const float*)d_in[9];
    const float* pb = (const float*)d_in[10];
    const float* lg = (const float*)d_in[11];
    const float* lb = (const float*)d_in[12];
    float* out = (float*)d_out;

    k_init<<<(NN + 255) / 256, 256>>>(ei);
    k_node<<<NN / ROWS_K1, 256>>>(x, Ww, Wb, aw);
    k_hist<<<NE / 256, 256>>>(ei);
    k_scanA<<<NB_SCAN, 1024>>>();
    k_scanB<<<NB_SCAN, 1024>>>();
    k_scatter<<<NE / 256, 256>>>(ei, et, ct, ab, dr);
    k_aggemm<<<NN / TB, 256>>>(pw, pb, x, lg, lb, out);
}